// round 1
// baseline (speedup 1.0000x reference)
#include <cuda_runtime.h>

#define NHEADS 6
#define DK 13
#define DKP 16
#define DIM 78
#define BATCH 8
#define SEQ 1024
#define OUT_ROWS 4099
#define OPSTR (8*6*1024*16)
#define SCALE 0.2773500981126146f
#define L2E 1.4426950408889634f

// scratch (device globals: no allocations allowed)
__device__ float g_Q[4*OPSTR];   // [op][b][h][i][16], pad dims 13..15 stay zero
__device__ float g_K[4*OPSTR];
__device__ float g_V[4*OPSTR];
__device__ float g_tok[8*3*78];

struct PtrPack {
    const float* x; const float* y; const float* z;
    const float* W[12];   // pid 0..3 Q(tv,ta,ctv,cta), 4..7 K, 8..11 V
};

__device__ __forceinline__ float ex2(float v) {
    float r; asm("ex2.approx.ftz.f32 %0, %1;" : "=f"(r) : "f"(v)); return r;
}

// ---------------------------------------------------------------------------
// Projections: out[b,i, c] = sum_k src[b,i,k] * W[k,c]; scatter into padded
// [op][b][h][i][16] head-major layout. 64 rows x 80 cols per block, 4x4 reg tile.
// ---------------------------------------------------------------------------
__global__ void __launch_bounds__(320) proj_kernel(PtrPack p) {
    int pid = blockIdx.y;
    const float* src = (pid < 4) ? p.x : (((pid & 1) == 0) ? p.y : p.z);
    const float* W = p.W[pid];
    float* dst = ((pid < 4) ? g_Q : (pid < 8 ? g_K : g_V)) + (pid & 3) * OPSTR;

    __shared__ float Ws[78][80];
    __shared__ float in_s[64][80];
    int tid = threadIdx.x;
    int row0 = blockIdx.x * 64;

    for (int idx = tid; idx < 78 * 80; idx += 320) {
        int k = idx / 80, c = idx % 80;
        Ws[k][c] = (c < 78) ? W[k * 78 + c] : 0.f;
    }
    for (int idx = tid; idx < 64 * 80; idx += 320) {
        int r = idx / 80, k = idx % 80;
        in_s[r][k] = (k < 78) ? src[(row0 + r) * 78 + k] : 0.f;
    }
    __syncthreads();

    int r0 = (tid / 20) * 4;
    int c0 = (tid % 20) * 4;
    float acc[4][4] = {};
    #pragma unroll 2
    for (int k = 0; k < 78; ++k) {
        float4 w = *(const float4*)&Ws[k][c0];
        #pragma unroll
        for (int i = 0; i < 4; ++i) {
            float a = in_s[r0 + i][k];
            acc[i][0] = fmaf(a, w.x, acc[i][0]);
            acc[i][1] = fmaf(a, w.y, acc[i][1]);
            acc[i][2] = fmaf(a, w.z, acc[i][2]);
            acc[i][3] = fmaf(a, w.w, acc[i][3]);
        }
    }
    #pragma unroll
    for (int i = 0; i < 4; ++i) {
        int rg = row0 + r0 + i;
        int bb = rg >> 10, ii = rg & 1023;
        #pragma unroll
        for (int j = 0; j < 4; ++j) {
            int c = c0 + j;
            if (c < 78) {
                int h = c / 13, dd = c % 13;
                dst[((bb * 6 + h) * 1024 + ii) * 16 + dd] = acc[i][j];
            }
        }
    }
}

// ---------------------------------------------------------------------------
// Attention. One thread per query row; K/V tiles of 256 keys staged in SMEM
// (64B rows -> broadcast LDS.128, conflict-free). op 0/1 cross (flash online),
// op 2/3 contrastive (pass1: max+Z, pass2: p -> exp(-p) -> weighted V, +q).
// Output row offsets: op0->0, op1->2048, op2->1024, op3->3072.
// ---------------------------------------------------------------------------
__device__ __forceinline__ float dot16(const float q[16], const float* ksrow) {
    const float4* k4 = (const float4*)ksrow;
    float4 a = k4[0], b = k4[1], c = k4[2], d = k4[3];
    float s0 = q[0]*a.x + q[1]*a.y + q[2]*a.z + q[3]*a.w;
    float s1 = q[4]*b.x + q[5]*b.y + q[6]*b.z + q[7]*b.w;
    float s2 = q[8]*c.x + q[9]*c.y + q[10]*c.z + q[11]*c.w;
    float s3 = q[12]*d.x + q[13]*d.y + q[14]*d.z + q[15]*d.w;
    return (s0 + s1) + (s2 + s3);
}

__global__ void __launch_bounds__(256) attn_kernel(float* __restrict__ out) {
    int op = blockIdx.z >> 3, b = blockIdx.z & 7;
    int h = blockIdx.y;
    int i = blockIdx.x * 256 + threadIdx.x;
    int base = ((op * 8 + b) * 6 + h) * 1024 * 16;
    const float* Q = g_Q + base;
    const float* K = g_K + base;
    const float* V = g_V + base;

    float q[16];
    {
        const float4* q4 = (const float4*)&Q[i * 16];
        float4 a = q4[0], bb = q4[1], c = q4[2], d = q4[3];
        q[0]=a.x; q[1]=a.y; q[2]=a.z; q[3]=a.w;
        q[4]=bb.x; q[5]=bb.y; q[6]=bb.z; q[7]=bb.w;
        q[8]=c.x; q[9]=c.y; q[10]=c.z; q[11]=c.w;
        q[12]=d.x; q[13]=d.y; q[14]=d.z; q[15]=d.w;
    }

    __shared__ float Ks[256][16];
    __shared__ float Vs[256][16];

    int rowoff = (op == 0) ? 0 : (op == 1 ? 2048 : (op == 2 ? 1024 : 3072));
    float* orow = out + ((size_t)b * OUT_ROWS + rowoff + i) * 78 + h * 13;

    if (op < 2) {
        // -------- cross attention, online softmax --------
        float m = -1e30f, Z = 0.f;
        float acc[16];
        #pragma unroll
        for (int d = 0; d < 16; ++d) acc[d] = 0.f;

        for (int t = 0; t < 4; ++t) {
            const float4* Kt = (const float4*)(K + t * 256 * 16);
            const float4* Vt = (const float4*)(V + t * 256 * 16);
            float4* Kd = (float4*)Ks;
            float4* Vd = (float4*)Vs;
            for (int idx = threadIdx.x; idx < 1024; idx += 256) {
                Kd[idx] = Kt[idx];
                Vd[idx] = Vt[idx];
            }
            __syncthreads();
            #pragma unroll 2
            for (int j = 0; j < 256; ++j) {
                float s = dot16(q, Ks[j]) * SCALE;
                if (s > m) {                   // rare (~log n times per row)
                    float cr = ex2((m - s) * L2E);
                    m = s; Z *= cr;
                    #pragma unroll
                    for (int d = 0; d < 16; ++d) acc[d] *= cr;
                }
                float pe = ex2((s - m) * L2E);
                Z += pe;
                const float4* v4 = (const float4*)Vs[j];
                float4 va = v4[0], vb = v4[1], vc = v4[2], vd = v4[3];
                acc[0]=fmaf(pe,va.x,acc[0]);  acc[1]=fmaf(pe,va.y,acc[1]);
                acc[2]=fmaf(pe,va.z,acc[2]);  acc[3]=fmaf(pe,va.w,acc[3]);
                acc[4]=fmaf(pe,vb.x,acc[4]);  acc[5]=fmaf(pe,vb.y,acc[5]);
                acc[6]=fmaf(pe,vb.z,acc[6]);  acc[7]=fmaf(pe,vb.w,acc[7]);
                acc[8]=fmaf(pe,vc.x,acc[8]);  acc[9]=fmaf(pe,vc.y,acc[9]);
                acc[10]=fmaf(pe,vc.z,acc[10]); acc[11]=fmaf(pe,vc.w,acc[11]);
                acc[12]=fmaf(pe,vd.x,acc[12]); acc[13]=fmaf(pe,vd.y,acc[13]);
                acc[14]=fmaf(pe,vd.z,acc[14]); acc[15]=fmaf(pe,vd.w,acc[15]);
            }
            __syncthreads();
        }
        float invZ = 1.f / Z;
        #pragma unroll
        for (int d = 0; d < 13; ++d) orow[d] = acc[d] * invZ;
    } else {
        // -------- contrastive: two passes --------
        float m = -1e30f, Z = 0.f;
        for (int t = 0; t < 4; ++t) {
            const float4* Kt = (const float4*)(K + t * 256 * 16);
            float4* Kd = (float4*)Ks;
            for (int idx = threadIdx.x; idx < 1024; idx += 256) Kd[idx] = Kt[idx];
            __syncthreads();
            #pragma unroll 2
            for (int j = 0; j < 256; ++j) {
                float s = dot16(q, Ks[j]) * SCALE;
                if (s > m) { Z *= ex2((m - s) * L2E); m = s; }
                Z += ex2((s - m) * L2E);
            }
            __syncthreads();
        }
        float invZ = 1.f / Z;
        float T = 0.f;
        float acc[16];
        #pragma unroll
        for (int d = 0; d < 16; ++d) acc[d] = 0.f;

        for (int t = 0; t < 4; ++t) {
            const float4* Kt = (const float4*)(K + t * 256 * 16);
            const float4* Vt = (const float4*)(V + t * 256 * 16);
            float4* Kd = (float4*)Ks;
            float4* Vd = (float4*)Vs;
            for (int idx = threadIdx.x; idx < 1024; idx += 256) {
                Kd[idx] = Kt[idx];
                Vd[idx] = Vt[idx];
            }
            __syncthreads();
            #pragma unroll 2
            for (int j = 0; j < 256; ++j) {
                float s = dot16(q, Ks[j]) * SCALE;
                float p = ex2((s - m) * L2E) * invZ;   // softmax1 prob
                float tt = ex2(-p * L2E);              // exp(1-p) up to const factor
                T += tt;
                const float4* v4 = (const float4*)Vs[j];
                float4 va = v4[0], vb = v4[1], vc = v4[2], vd = v4[3];
                acc[0]=fmaf(tt,va.x,acc[0]);  acc[1]=fmaf(tt,va.y,acc[1]);
                acc[2]=fmaf(tt,va.z,acc[2]);  acc[3]=fmaf(tt,va.w,acc[3]);
                acc[4]=fmaf(tt,vb.x,acc[4]);  acc[5]=fmaf(tt,vb.y,acc[5]);
                acc[6]=fmaf(tt,vb.z,acc[6]);  acc[7]=fmaf(tt,vb.w,acc[7]);
                acc[8]=fmaf(tt,vc.x,acc[8]);  acc[9]=fmaf(tt,vc.y,acc[9]);
                acc[10]=fmaf(tt,vc.z,acc[10]); acc[11]=fmaf(tt,vc.w,acc[11]);
                acc[12]=fmaf(tt,vd.x,acc[12]); acc[13]=fmaf(tt,vd.y,acc[13]);
                acc[14]=fmaf(tt,vd.z,acc[14]); acc[15]=fmaf(tt,vd.w,acc[15]);
            }
            __syncthreads();
        }
        float invT = 1.f / T;
        #pragma unroll
        for (int d = 0; d < 13; ++d) orow[d] = q[d] + acc[d] * invT;
    }
}

// ---------------------------------------------------------------------------
// Pooled tokens: tok0 = mean(x), tok1 = mean(rows 0..2047 of out),
// tok2 = mean(rows 2048..4095 of out); each divided by 1024 (pairwise sum).
// ---------------------------------------------------------------------------
__global__ void mean_kernel(const float* __restrict__ x, const float* __restrict__ out) {
    int b = blockIdx.x, tok = blockIdx.y, t = threadIdx.x;
    if (t >= 78) return;
    float s = 0.f;
    if (tok == 0) {
        const float* px = x + (size_t)b * 1024 * 78 + t;
        for (int i = 0; i < 1024; ++i) s += px[(size_t)i * 78];
    } else {
        int r0 = (tok == 1) ? 0 : 2048;
        const float* po = out + ((size_t)b * OUT_ROWS + r0) * 78 + t;
        for (int i = 0; i < 2048; ++i) s += po[(size_t)i * 78];
    }
    g_tok[(b * 3 + tok) * 78 + t] = s * (1.f / 1024.f);
}

// ---------------------------------------------------------------------------
// Tiny 3-token MHSA on pooled tokens -> output rows 4096..4098.
// ---------------------------------------------------------------------------
__global__ void fused_kernel(const float* __restrict__ Wq, const float* __restrict__ Wk,
                             const float* __restrict__ Wv, float* __restrict__ out) {
    __shared__ float tok[3][78];
    __shared__ float qs[3][78], ks[3][78], vs[3][78];
    __shared__ float ps[6][3][3];
    int b = blockIdx.x, t = threadIdx.x;

    for (int idx = t; idx < 234; idx += 96) tok[idx / 78][idx % 78] = g_tok[b * 234 + idx];
    __syncthreads();

    if (t < 78) {
        for (int i = 0; i < 3; ++i) {
            float qa = 0.f, ka = 0.f, va = 0.f;
            for (int c = 0; c < 78; ++c) {
                float tv = tok[i][c];
                qa = fmaf(tv, Wq[c * 78 + t], qa);
                ka = fmaf(tv, Wk[c * 78 + t], ka);
                va = fmaf(tv, Wv[c * 78 + t], va);
            }
            qs[i][t] = qa; ks[i][t] = ka; vs[i][t] = va;
        }
    }
    __syncthreads();

    if (t < 54) {
        int h = t / 9, rem = t % 9, i = rem / 3, j = rem % 3;
        float s = 0.f;
        for (int d = 0; d < 13; ++d) s = fmaf(qs[i][h * 13 + d], ks[j][h * 13 + d], s);
        ps[h][i][j] = s * SCALE;
    }
    __syncthreads();

    if (t < 18) {
        int h = t / 3, i = t % 3;
        float a = ps[h][i][0], bb = ps[h][i][1], c = ps[h][i][2];
        float mx = fmaxf(a, fmaxf(bb, c));
        float ea = ex2((a - mx) * L2E), eb = ex2((bb - mx) * L2E), ec = ex2((c - mx) * L2E);
        float inv = 1.f / (ea + eb + ec);
        ps[h][i][0] = ea * inv; ps[h][i][1] = eb * inv; ps[h][i][2] = ec * inv;
    }
    __syncthreads();

    if (t < 78) {
        int h = t / 13;
        for (int i = 0; i < 3; ++i) {
            float o = ps[h][i][0] * vs[0][t] + ps[h][i][1] * vs[1][t] + ps[h][i][2] * vs[2][t];
            out[((size_t)b * OUT_ROWS + 4096 + i) * 78 + t] = o;
        }
    }
}

// ---------------------------------------------------------------------------
extern "C" void kernel_launch(void* const* d_in, const int* in_sizes, int n_in,
                              void* d_out, int out_size) {
    // metadata order: x,y,z,mask_tv,mask_ta, Wq_tv,Wk_tv,Wv_tv, Wq_ta,Wk_ta,Wv_ta,
    //                 Wq_ctv,Wk_ctv,Wv_ctv, Wq_cta,Wk_cta,Wv_cta, Wq_s,Wk_s,Wv_s
    PtrPack p;
    p.x = (const float*)d_in[0];
    p.y = (const float*)d_in[1];
    p.z = (const float*)d_in[2];
    const int widx[12] = {5, 8, 11, 14,   // Q: tv, ta, ctv, cta
                          6, 9, 12, 15,   // K
                          7, 10, 13, 16}; // V
    for (int i = 0; i < 12; ++i) p.W[i] = (const float*)d_in[widx[i]];
    float* out = (float*)d_out;

    proj_kernel<<<dim3(128, 12), 320>>>(p);
    attn_kernel<<<dim3(4, 6, 32), 256>>>(out);
    mean_kernel<<<dim3(8, 3), 96>>>((const float*)d_in[0], out);
    fused_kernel<<<8, 96>>>((const float*)d_in[17], (const float*)d_in[18],
                            (const float*)d_in[19], out);
}

// round 2
// speedup vs baseline: 1.0776x; 1.0776x over previous
#include <cuda_runtime.h>

typedef unsigned long long ull;

#define OUT_ROWS 4099
#define OPSTR (8*6*1024*16)
#define SCALE 0.2773500981126146f
#define L2E   1.4426950408889634f
#define CQ    (SCALE*L2E)
#define TKEYS 128

// scratch (device globals: no allocations allowed)
__device__ float g_Q[4*OPSTR];   // [op][b][h][i][16], pads 13..15 stay zero
__device__ float g_K[4*OPSTR];
__device__ float g_V[4*OPSTR];
__device__ float g_tok[8*3*78];

struct PtrPack {
    const float* x; const float* y; const float* z;
    const float* W[12];   // 0..3 Q(tv,ta,ctv,cta), 4..7 K, 8..11 V
};

// ---------------- packed f32x2 helpers ----------------
__device__ __forceinline__ float ex2(float v) {
    float r; asm("ex2.approx.ftz.f32 %0, %1;" : "=f"(r) : "f"(v)); return r;
}
__device__ __forceinline__ float lg2(float v) {
    float r; asm("lg2.approx.ftz.f32 %0, %1;" : "=f"(r) : "f"(v)); return r;
}
__device__ __forceinline__ ull pk(float lo, float hi) {
    ull r; asm("mov.b64 %0, {%1,%2};" : "=l"(r) : "f"(lo), "f"(hi)); return r;
}
__device__ __forceinline__ void upk(ull v, float& lo, float& hi) {
    asm("mov.b64 {%0,%1}, %2;" : "=f"(lo), "=f"(hi) : "l"(v));
}
__device__ __forceinline__ ull fma2(ull a, ull b, ull c) {
    ull d; asm("fma.rn.f32x2 %0, %1, %2, %3;" : "=l"(d) : "l"(a), "l"(b), "l"(c)); return d;
}
__device__ __forceinline__ ull add2(ull a, ull b) {
    ull d; asm("add.rn.f32x2 %0, %1, %2;" : "=l"(d) : "l"(a), "l"(b)); return d;
}

// ---------------------------------------------------------------------------
// Projections (unchanged from R1): [b,i,c] -> padded [op][b][h][i][16]
// ---------------------------------------------------------------------------
__global__ void __launch_bounds__(320) proj_kernel(PtrPack p) {
    int pid = blockIdx.y;
    const float* src = (pid < 4) ? p.x : (((pid & 1) == 0) ? p.y : p.z);
    const float* W = p.W[pid];
    float* dst = ((pid < 4) ? g_Q : (pid < 8 ? g_K : g_V)) + (pid & 3) * OPSTR;

    __shared__ float Ws[78][80];
    __shared__ float in_s[64][80];
    int tid = threadIdx.x;
    int row0 = blockIdx.x * 64;

    for (int idx = tid; idx < 78 * 80; idx += 320) {
        int k = idx / 80, c = idx % 80;
        Ws[k][c] = (c < 78) ? W[k * 78 + c] : 0.f;
    }
    for (int idx = tid; idx < 64 * 80; idx += 320) {
        int r = idx / 80, k = idx % 80;
        in_s[r][k] = (k < 78) ? src[(row0 + r) * 78 + k] : 0.f;
    }
    __syncthreads();

    int r0 = (tid / 20) * 4;
    int c0 = (tid % 20) * 4;
    float acc[4][4] = {};
    #pragma unroll 2
    for (int k = 0; k < 78; ++k) {
        float4 w = *(const float4*)&Ws[k][c0];
        #pragma unroll
        for (int i = 0; i < 4; ++i) {
            float a = in_s[r0 + i][k];
            acc[i][0] = fmaf(a, w.x, acc[i][0]);
            acc[i][1] = fmaf(a, w.y, acc[i][1]);
            acc[i][2] = fmaf(a, w.z, acc[i][2]);
            acc[i][3] = fmaf(a, w.w, acc[i][3]);
        }
    }
    #pragma unroll
    for (int i = 0; i < 4; ++i) {
        int rg = row0 + r0 + i;
        int bb = rg >> 10, ii = rg & 1023;
        #pragma unroll
        for (int j = 0; j < 4; ++j) {
            int c = c0 + j;
            if (c < 78) {
                int h = c / 13, dd = c % 13;
                dst[((bb * 6 + h) * 1024 + ii) * 16 + dd] = acc[i][j];
            }
        }
    }
}

// ---------------------------------------------------------------------------
// Stage a 128-key x 16-dim tile into SMEM with every scalar DUPLICATED into a
// float2 pair -> mainloop reads (v,v) packed operands directly (no pack instrs).
// ---------------------------------------------------------------------------
__device__ __forceinline__ void stage_dup(const float* __restrict__ src,
                                          float (*dst)[32], int tid) {
    const float4* s4 = (const float4*)src;
    #pragma unroll
    for (int idx = tid; idx < TKEYS * 4; idx += 256) {
        int key = idx >> 2, part = idx & 3;
        float4 v = s4[idx];
        float2* d = (float2*)&dst[key][part * 8];
        d[0] = make_float2(v.x, v.x);
        d[1] = make_float2(v.y, v.y);
        d[2] = make_float2(v.z, v.z);
        d[3] = make_float2(v.w, v.w);
    }
}

// ---------------------------------------------------------------------------
// Attention: one thread handles TWO query rows via packed f32x2 math.
// No max-tracking (scores are O(1), exp cannot overflow; softmax shift-inv).
// op 0/1 cross (single pass), op 2/3 contrastive (Z pass + weighted pass).
// ---------------------------------------------------------------------------
__global__ void __launch_bounds__(256) attn_kernel(float* __restrict__ out) {
    int op = blockIdx.z >> 3, b = blockIdx.z & 7;
    int h = blockIdx.y;
    int i0 = (blockIdx.x * 256 + threadIdx.x) * 2;   // queries i0, i0+1
    int tid = threadIdx.x;
    int base = ((op * 8 + b) * 6 + h) * 1024 * 16;
    const float* Q = g_Q + base;
    const float* K = g_K + base;
    const float* V = g_V + base;

    __shared__ float Ks2[TKEYS][32];
    __shared__ float Vs2[TKEYS][32];

    // load the two query rows, pre-scaled by SCALE*log2(e), packed per-dim
    ull qp[14];
    {
        const float4* qa = (const float4*)&Q[i0 * 16];
        const float4* qb = (const float4*)&Q[(i0 + 1) * 16];
        float f0[16], f1[16];
        #pragma unroll
        for (int p = 0; p < 4; ++p) {
            float4 a = qa[p], bq = qb[p];
            f0[4*p] = a.x; f0[4*p+1] = a.y; f0[4*p+2] = a.z; f0[4*p+3] = a.w;
            f1[4*p] = bq.x; f1[4*p+1] = bq.y; f1[4*p+2] = bq.z; f1[4*p+3] = bq.w;
        }
        #pragma unroll
        for (int d = 0; d < 14; ++d) qp[d] = pk(f0[d] * CQ, f1[d] * CQ);
    }

    int rowoff = (op == 0) ? 0 : (op == 1 ? 2048 : (op == 2 ? 1024 : 3072));
    float* o0 = out + ((size_t)b * OUT_ROWS + rowoff + i0) * 78 + h * 13;
    float* o1 = o0 + 78;

    if (op < 2) {
        // ---------- cross attention, single pass, no max ----------
        ull Zp = 0ULL;
        ull acc[14];
        #pragma unroll
        for (int d = 0; d < 14; ++d) acc[d] = 0ULL;

        for (int t = 0; t < 1024 / TKEYS; ++t) {
            stage_dup(K + t * TKEYS * 16, Ks2, tid);
            stage_dup(V + t * TKEYS * 16, Vs2, tid);
            __syncthreads();
            #pragma unroll 2
            for (int j = 0; j < TKEYS; ++j) {
                const ulonglong2* kr = (const ulonglong2*)Ks2[j];
                ull c0 = 0ULL, c1 = 0ULL;
                #pragma unroll
                for (int p = 0; p < 7; ++p) {
                    ulonglong2 kk = kr[p];
                    c0 = fma2(qp[2*p],     kk.x, c0);
                    c1 = fma2(qp[2*p + 1], kk.y, c1);
                }
                float s0, s1; upk(add2(c0, c1), s0, s1);
                ull ep = pk(ex2(s0), ex2(s1));
                Zp = add2(Zp, ep);
                const ulonglong2* vr = (const ulonglong2*)Vs2[j];
                #pragma unroll
                for (int p = 0; p < 7; ++p) {
                    ulonglong2 vv = vr[p];
                    acc[2*p]     = fma2(ep, vv.x, acc[2*p]);
                    acc[2*p + 1] = fma2(ep, vv.y, acc[2*p + 1]);
                }
            }
            __syncthreads();
        }
        float Z0, Z1; upk(Zp, Z0, Z1);
        float iz0 = 1.f / Z0, iz1 = 1.f / Z1;
        #pragma unroll
        for (int d = 0; d < 13; ++d) {
            float a0, a1; upk(acc[d], a0, a1);
            o0[d] = a0 * iz0;
            o1[d] = a1 * iz1;
        }
    } else {
        // ---------- contrastive: pass 1 (Z only) ----------
        ull Zp = 0ULL;
        for (int t = 0; t < 1024 / TKEYS; ++t) {
            stage_dup(K + t * TKEYS * 16, Ks2, tid);
            __syncthreads();
            #pragma unroll 2
            for (int j = 0; j < TKEYS; ++j) {
                const ulonglong2* kr = (const ulonglong2*)Ks2[j];
                ull c0 = 0ULL, c1 = 0ULL;
                #pragma unroll
                for (int p = 0; p < 7; ++p) {
                    ulonglong2 kk = kr[p];
                    c0 = fma2(qp[2*p],     kk.x, c0);
                    c1 = fma2(qp[2*p + 1], kk.y, c1);
                }
                float s0, s1; upk(add2(c0, c1), s0, s1);
                Zp = add2(Zp, pk(ex2(s0), ex2(s1)));
            }
            __syncthreads();
        }
        float Z0, Z1; upk(Zp, Z0, Z1);
        // fold -log2(Z) into the dot init: p = 2^(dot' - log2 Z)
        ull initp = pk(-lg2(Z0), -lg2(Z1));

        // ---------- pass 2: p -> exp(-p), weighted V ----------
        ull Tp = 0ULL;
        ull acc[14];
        #pragma unroll
        for (int d = 0; d < 14; ++d) acc[d] = 0ULL;

        for (int t = 0; t < 1024 / TKEYS; ++t) {
            stage_dup(K + t * TKEYS * 16, Ks2, tid);
            stage_dup(V + t * TKEYS * 16, Vs2, tid);
            __syncthreads();
            #pragma unroll 2
            for (int j = 0; j < TKEYS; ++j) {
                const ulonglong2* kr = (const ulonglong2*)Ks2[j];
                ull c0 = initp, c1 = 0ULL;
                #pragma unroll
                for (int p = 0; p < 7; ++p) {
                    ulonglong2 kk = kr[p];
                    c0 = fma2(qp[2*p],     kk.x, c0);
                    c1 = fma2(qp[2*p + 1], kk.y, c1);
                }
                float s0, s1; upk(add2(c0, c1), s0, s1);
                float p0 = ex2(s0), p1 = ex2(s1);            // softmax1 probs
                float t0 = ex2(p0 * (-L2E));                 // exp(-p)
                float t1 = ex2(p1 * (-L2E));
                ull tp = pk(t0, t1);
                Tp = add2(Tp, tp);
                const ulonglong2* vr = (const ulonglong2*)Vs2[j];
                #pragma unroll
                for (int p = 0; p < 7; ++p) {
                    ulonglong2 vv = vr[p];
                    acc[2*p]     = fma2(tp, vv.x, acc[2*p]);
                    acc[2*p + 1] = fma2(tp, vv.y, acc[2*p + 1]);
                }
            }
            __syncthreads();
        }
        float T0, T1; upk(Tp, T0, T1);
        float it0 = 1.f / T0, it1 = 1.f / T1;
        const float* qr0 = &Q[i0 * 16];
        const float* qr1 = &Q[(i0 + 1) * 16];
        #pragma unroll
        for (int d = 0; d < 13; ++d) {
            float a0, a1; upk(acc[d], a0, a1);
            o0[d] = qr0[d] + a0 * it0;
            o1[d] = qr1[d] + a1 * it1;
        }
    }
}

// ---------------------------------------------------------------------------
// Pooled tokens: 8-way row split per (b, tok) + smem reduce.
// ---------------------------------------------------------------------------
__global__ void __launch_bounds__(640) mean_kernel(const float* __restrict__ x,
                                                   const float* __restrict__ out) {
    __shared__ float red[8][78];
    int b = blockIdx.x, tok = blockIdx.y, t = threadIdx.x;
    if (t < 624) {
        int g = t / 78, c = t % 78;
        float s = 0.f;
        if (tok == 0) {
            const float* p = x + (size_t)b * 1024 * 78 + c;
            for (int i = g; i < 1024; i += 8) s += p[(size_t)i * 78];
        } else {
            int r0 = (tok == 1) ? 0 : 2048;
            const float* p = out + ((size_t)b * OUT_ROWS + r0) * 78 + c;
            for (int i = g; i < 2048; i += 8) s += p[(size_t)i * 78];
        }
        red[g][c] = s;
    }
    __syncthreads();
    if (t < 78) {
        float tot = 0.f;
        #pragma unroll
        for (int g = 0; g < 8; ++g) tot += red[g][t];
        g_tok[(b * 3 + tok) * 78 + t] = tot * (1.f / 1024.f);
    }
}

// ---------------------------------------------------------------------------
// Tiny 3-token MHSA: one thread per (component, token, col) for the projection.
// ---------------------------------------------------------------------------
__global__ void __launch_bounds__(704) fused_kernel(const float* __restrict__ Wq,
                                                    const float* __restrict__ Wk,
                                                    const float* __restrict__ Wv,
                                                    float* __restrict__ out) {
    __shared__ float tok[3][78];
    __shared__ float qs[3][78], ks[3][78], vs[3][78];
    __shared__ float ps[6][3][3];
    int b = blockIdx.x, t = threadIdx.x;

    for (int idx = t; idx < 234; idx += 704) tok[idx / 78][idx % 78] = g_tok[b * 234 + idx];
    __syncthreads();

    if (t < 702) {
        int comp = t / 234, rem = t % 234, i = rem / 78, c = rem % 78;
        const float* W = (comp == 0) ? Wq : ((comp == 1) ? Wk : Wv);
        float a = 0.f;
        #pragma unroll 6
        for (int k = 0; k < 78; ++k) a = fmaf(tok[i][k], W[k * 78 + c], a);
        float (*dst)[78] = (comp == 0) ? qs : ((comp == 1) ? ks : vs);
        dst[i][c] = a;
    }
    __syncthreads();

    if (t < 54) {
        int h = t / 9, rem = t % 9, i = rem / 3, j = rem % 3;
        float s = 0.f;
        #pragma unroll
        for (int d = 0; d < 13; ++d) s = fmaf(qs[i][h * 13 + d], ks[j][h * 13 + d], s);
        ps[h][i][j] = s * SCALE;
    }
    __syncthreads();

    if (t < 18) {
        int h = t / 3, i = t % 3;
        float a = ps[h][i][0], bb = ps[h][i][1], c = ps[h][i][2];
        float mx = fmaxf(a, fmaxf(bb, c));
        float ea = ex2((a - mx) * L2E), eb = ex2((bb - mx) * L2E), ec = ex2((c - mx) * L2E);
        float inv = 1.f / (ea + eb + ec);
        ps[h][i][0] = ea * inv; ps[h][i][1] = eb * inv; ps[h][i][2] = ec * inv;
    }
    __syncthreads();

    if (t < 78) {
        int h = t / 13;
        #pragma unroll
        for (int i = 0; i < 3; ++i) {
            float o = ps[h][i][0] * vs[0][t] + ps[h][i][1] * vs[1][t] + ps[h][i][2] * vs[2][t];
            out[((size_t)b * OUT_ROWS + 4096 + i) * 78 + t] = o;
        }
    }
}

// ---------------------------------------------------------------------------
extern "C" void kernel_launch(void* const* d_in, const int* in_sizes, int n_in,
                              void* d_out, int out_size) {
    PtrPack p;
    p.x = (const float*)d_in[0];
    p.y = (const float*)d_in[1];
    p.z = (const float*)d_in[2];
    const int widx[12] = {5, 8, 11, 14,   // Q: tv, ta, ctv, cta
                          6, 9, 12, 15,   // K
                          7, 10, 13, 16}; // V
    for (int i = 0; i < 12; ++i) p.W[i] = (const float*)d_in[widx[i]];
    float* out = (float*)d_out;

    proj_kernel<<<dim3(128, 12), 320>>>(p);
    attn_kernel<<<dim3(2, 6, 32), 256>>>(out);
    mean_kernel<<<dim3(8, 3), 640>>>((const float*)d_in[0], out);
    fused_kernel<<<8, 704>>>((const float*)d_in[17], (const float*)d_in[18],
                             (const float*)d_in[19], out);
}

// round 4
// speedup vs baseline: 1.6681x; 1.5481x over previous
#include <cuda_runtime.h>

typedef unsigned long long ull;

#define OUT_ROWS 4099
#define OPSTR (8*6*1024*16)
#define SCALE 0.2773500981126146f
#define L2E   1.4426950408889634f
#define NL2E  (-1.4426950408889634f)
#define CQ    (SCALE*L2E)
#define TKEYS 128

// scratch (device globals zero-initialized; pad dims 13..15 never written)
__device__ float g_Q[4*OPSTR];   // [op][b][h][i][16]
__device__ float g_K[4*OPSTR];   // [op][b][h][pair][dim][2]  pair-interleaved
__device__ float g_V[4*OPSTR];   // same layout as K
__device__ float g_tok[8*3*78];

struct PtrPack {
    const float* x; const float* y; const float* z;
    const float* W[12];   // 0..3 Q(tv,ta,ctv,cta), 4..7 K, 8..11 V
};

__device__ __forceinline__ float ex2(float v) {
    float r; asm("ex2.approx.ftz.f32 %0, %1;" : "=f"(r) : "f"(v)); return r;
}
__device__ __forceinline__ float lg2(float v) {
    float r; asm("lg2.approx.ftz.f32 %0, %1;" : "=f"(r) : "f"(v)); return r;
}
__device__ __forceinline__ ull pk(float lo, float hi) {
    ull r; asm("mov.b64 %0, {%1,%2};" : "=l"(r) : "f"(lo), "f"(hi)); return r;
}
__device__ __forceinline__ void upk(ull v, float& lo, float& hi) {
    asm("mov.b64 {%0,%1}, %2;" : "=f"(lo), "=f"(hi) : "l"(v));
}
__device__ __forceinline__ ull fma2(ull a, ull b, ull c) {
    ull d; asm("fma.rn.f32x2 %0, %1, %2, %3;" : "=l"(d) : "l"(a), "l"(b), "l"(c)); return d;
}
__device__ __forceinline__ ull add2(ull a, ull b) {
    ull d; asm("add.rn.f32x2 %0, %1, %2;" : "=l"(d) : "l"(a), "l"(b)); return d;
}

// ---------------------------------------------------------------------------
// Projections: [b,i,c] -> Q padded [i][16]; K/V pair-interleaved [i>>1][d][i&1]
// ---------------------------------------------------------------------------
__global__ void __launch_bounds__(320) proj_kernel(PtrPack p) {
    int pid = blockIdx.y;
    const float* src = (pid < 4) ? p.x : (((pid & 1) == 0) ? p.y : p.z);
    const float* W = p.W[pid];
    float* dst = ((pid < 4) ? g_Q : (pid < 8 ? g_K : g_V)) + (pid & 3) * OPSTR;
    bool isQ = (pid < 4);

    __shared__ float Ws[78][80];
    __shared__ float in_s[64][80];
    int tid = threadIdx.x;
    int row0 = blockIdx.x * 64;

    for (int idx = tid; idx < 78 * 80; idx += 320) {
        int k = idx / 80, c = idx % 80;
        Ws[k][c] = (c < 78) ? W[k * 78 + c] : 0.f;
    }
    for (int idx = tid; idx < 64 * 80; idx += 320) {
        int r = idx / 80, k = idx % 80;
        in_s[r][k] = (k < 78) ? src[(row0 + r) * 78 + k] : 0.f;
    }
    __syncthreads();

    int r0 = (tid / 20) * 4;
    int c0 = (tid % 20) * 4;
    float acc[4][4] = {};
    #pragma unroll 2
    for (int k = 0; k < 78; ++k) {
        float4 w = *(const float4*)&Ws[k][c0];
        #pragma unroll
        for (int i = 0; i < 4; ++i) {
            float a = in_s[r0 + i][k];
            acc[i][0] = fmaf(a, w.x, acc[i][0]);
            acc[i][1] = fmaf(a, w.y, acc[i][1]);
            acc[i][2] = fmaf(a, w.z, acc[i][2]);
            acc[i][3] = fmaf(a, w.w, acc[i][3]);
        }
    }
    #pragma unroll
    for (int i = 0; i < 4; ++i) {
        int rg = row0 + r0 + i;
        int bb = rg >> 10, ii = rg & 1023;
        #pragma unroll
        for (int j = 0; j < 4; ++j) {
            int c = c0 + j;
            if (c < 78) {
                int h = c / 13, dd = c % 13;
                int base = (bb * 6 + h) * 16384;
                int off = isQ ? (ii * 16 + dd)
                              : ((ii >> 1) * 32 + dd * 2 + (ii & 1));
                dst[base + off] = acc[i][j];
            }
        }
    }
}

// ---------------------------------------------------------------------------
// Attention: thread = 2 queries; iteration = 2 keys (pair-interleaved SMEM).
// f32x2 lanes carry (even key, odd key). No max-tracking (scores O(1)).
// ---------------------------------------------------------------------------
__global__ void __launch_bounds__(256) attn_kernel(float* __restrict__ out) {
    int op = blockIdx.z >> 3, b = blockIdx.z & 7;
    int h = blockIdx.y;
    int tid = threadIdx.x;
    int i0 = (blockIdx.x * 256 + tid) * 2;
    int base = ((op * 8 + b) * 6 + h) * 16384;
    const float* Q = g_Q + base;
    const float* K = g_K + base;
    const float* V = g_V + base;

    __shared__ float Ks2[TKEYS * 16];   // 8KB: [pair][dim][2]
    __shared__ float Vs2[TKEYS * 16];

    // two query rows, dims pre-scaled by SCALE*log2e, each dim dup-packed
    ull qd[2][14];
    #pragma unroll
    for (int u = 0; u < 2; ++u) {
        const float4* q4 = (const float4*)&Q[(i0 + u) * 16];
        #pragma unroll
        for (int p = 0; p < 4; ++p) {
            float4 a = q4[p];
            if (4 * p     < 14) { float v = a.x * CQ; qd[u][4*p]     = pk(v, v); }
            if (4 * p + 1 < 14) { float v = a.y * CQ; qd[u][4*p + 1] = pk(v, v); }
            if (4 * p + 2 < 14) { float v = a.z * CQ; qd[u][4*p + 2] = pk(v, v); }
            if (4 * p + 3 < 14) { float v = a.w * CQ; qd[u][4*p + 3] = pk(v, v); }
        }
    }

    int rowoff = (op == 0) ? 0 : (op == 1 ? 2048 : (op == 2 ? 1024 : 3072));
    float* o0 = out + ((size_t)b * OUT_ROWS + rowoff + i0) * 78 + h * 13;
    float* o1 = o0 + 78;

    if (op < 2) {
        // ---------------- cross attention, single pass ----------------
        ull Zp0 = 0, Zp1 = 0;
        ull acc0[14], acc1[14];
        #pragma unroll
        for (int d = 0; d < 14; ++d) { acc0[d] = 0; acc1[d] = 0; }

        for (int t = 0; t < 1024 / TKEYS; ++t) {
            const float4* Kt = (const float4*)(K + t * TKEYS * 16);
            const float4* Vt = (const float4*)(V + t * TKEYS * 16);
            #pragma unroll
            for (int idx = tid; idx < TKEYS * 4; idx += 256) {
                ((float4*)Ks2)[idx] = Kt[idx];
                ((float4*)Vs2)[idx] = Vt[idx];
            }
            __syncthreads();
            #pragma unroll 2
            for (int j = 0; j < TKEYS / 2; ++j) {
                const ulonglong2* kr = (const ulonglong2*)(Ks2 + j * 32);
                ull c00 = 0, c01 = 0, c10 = 0, c11 = 0;
                #pragma unroll
                for (int p = 0; p < 7; ++p) {
                    ulonglong2 kk = kr[p];
                    c00 = fma2(qd[0][2*p],     kk.x, c00);
                    c01 = fma2(qd[0][2*p + 1], kk.y, c01);
                    c10 = fma2(qd[1][2*p],     kk.x, c10);
                    c11 = fma2(qd[1][2*p + 1], kk.y, c11);
                }
                float s0a, s0b, s1a, s1b;
                upk(add2(c00, c01), s0a, s0b);
                upk(add2(c10, c11), s1a, s1b);
                ull e0 = pk(ex2(s0a), ex2(s0b));
                ull e1 = pk(ex2(s1a), ex2(s1b));
                Zp0 = add2(Zp0, e0);
                Zp1 = add2(Zp1, e1);
                const ulonglong2* vr = (const ulonglong2*)(Vs2 + j * 32);
                #pragma unroll
                for (int p = 0; p < 7; ++p) {
                    ulonglong2 vv = vr[p];
                    acc0[2*p]     = fma2(e0, vv.x, acc0[2*p]);
                    acc0[2*p + 1] = fma2(e0, vv.y, acc0[2*p + 1]);
                    acc1[2*p]     = fma2(e1, vv.x, acc1[2*p]);
                    acc1[2*p + 1] = fma2(e1, vv.y, acc1[2*p + 1]);
                }
            }
            __syncthreads();
        }
        float za, zb;
        upk(Zp0, za, zb); float iz0 = 1.f / (za + zb);
        upk(Zp1, za, zb); float iz1 = 1.f / (za + zb);
        #pragma unroll
        for (int d = 0; d < 13; ++d) {
            float aa, ab;
            upk(acc0[d], aa, ab); o0[d] = (aa + ab) * iz0;
            upk(acc1[d], aa, ab); o1[d] = (aa + ab) * iz1;
        }
    } else {
        // ---------------- contrastive: pass 1 (Z only) ----------------
        ull Zp0 = 0, Zp1 = 0;
        for (int t = 0; t < 1024 / TKEYS; ++t) {
            const float4* Kt = (const float4*)(K + t * TKEYS * 16);
            #pragma unroll
            for (int idx = tid; idx < TKEYS * 4; idx += 256)
                ((float4*)Ks2)[idx] = Kt[idx];
            __syncthreads();
            #pragma unroll 2
            for (int j = 0; j < TKEYS / 2; ++j) {
                const ulonglong2* kr = (const ulonglong2*)(Ks2 + j * 32);
                ull c00 = 0, c01 = 0, c10 = 0, c11 = 0;
                #pragma unroll
                for (int p = 0; p < 7; ++p) {
                    ulonglong2 kk = kr[p];
                    c00 = fma2(qd[0][2*p],     kk.x, c00);
                    c01 = fma2(qd[0][2*p + 1], kk.y, c01);
                    c10 = fma2(qd[1][2*p],     kk.x, c10);
                    c11 = fma2(qd[1][2*p + 1], kk.y, c11);
                }
                float s0a, s0b, s1a, s1b;
                upk(add2(c00, c01), s0a, s0b);
                upk(add2(c10, c11), s1a, s1b);
                Zp0 = add2(Zp0, pk(ex2(s0a), ex2(s0b)));
                Zp1 = add2(Zp1, pk(ex2(s1a), ex2(s1b)));
            }
            __syncthreads();
        }
        float za, zb;
        upk(Zp0, za, zb); float il0 = -lg2(za + zb);
        upk(Zp1, za, zb); float il1 = -lg2(za + zb);
        ull init0 = pk(il0, il0), init1 = pk(il1, il1);

        // -------- pass 2: p = 2^(s - log2 Z); w = exp(-p); weighted V --------
        ull Tp0 = 0, Tp1 = 0;
        ull acc0[14], acc1[14];
        #pragma unroll
        for (int d = 0; d < 14; ++d) { acc0[d] = 0; acc1[d] = 0; }

        for (int t = 0; t < 1024 / TKEYS; ++t) {
            const float4* Kt = (const float4*)(K + t * TKEYS * 16);
            const float4* Vt = (const float4*)(V + t * TKEYS * 16);
            #pragma unroll
            for (int idx = tid; idx < TKEYS * 4; idx += 256) {
                ((float4*)Ks2)[idx] = Kt[idx];
                ((float4*)Vs2)[idx] = Vt[idx];
            }
            __syncthreads();
            #pragma unroll 2
            for (int j = 0; j < TKEYS / 2; ++j) {
                const ulonglong2* kr = (const ulonglong2*)(Ks2 + j * 32);
                ull c00 = init0, c01 = 0, c10 = init1, c11 = 0;
                #pragma unroll
                for (int p = 0; p < 7; ++p) {
                    ulonglong2 kk = kr[p];
                    c00 = fma2(qd[0][2*p],     kk.x, c00);
                    c01 = fma2(qd[0][2*p + 1], kk.y, c01);
                    c10 = fma2(qd[1][2*p],     kk.x, c10);
                    c11 = fma2(qd[1][2*p + 1], kk.y, c11);
                }
                float s0a, s0b, s1a, s1b;
                upk(add2(c00, c01), s0a, s0b);
                upk(add2(c10, c11), s1a, s1b);
                float t0a = ex2(ex2(s0a) * NL2E);
                float t0b = ex2(ex2(s0b) * NL2E);
                float t1a = ex2(ex2(s1a) * NL2E);
                float t1b = ex2(ex2(s1b) * NL2E);
                ull e0 = pk(t0a, t0b);
                ull e1 = pk(t1a, t1b);
                Tp0 = add2(Tp0, e0);
                Tp1 = add2(Tp1, e1);
                const ulonglong2* vr = (const ulonglong2*)(Vs2 + j * 32);
                #pragma unroll
                for (int p = 0; p < 7; ++p) {
                    ulonglong2 vv = vr[p];
                    acc0[2*p]     = fma2(e0, vv.x, acc0[2*p]);
                    acc0[2*p + 1] = fma2(e0, vv.y, acc0[2*p + 1]);
                    acc1[2*p]     = fma2(e1, vv.x, acc1[2*p]);
                    acc1[2*p + 1] = fma2(e1, vv.y, acc1[2*p + 1]);
                }
            }
            __syncthreads();
        }
        float ta, tb;
        upk(Tp0, ta, tb); float it0 = 1.f / (ta + tb);
        upk(Tp1, ta, tb); float it1 = 1.f / (ta + tb);
        const float* qr0 = &Q[i0 * 16];
        const float* qr1 = &Q[(i0 + 1) * 16];
        #pragma unroll
        for (int d = 0; d < 13; ++d) {
            float aa, ab;
            upk(acc0[d], aa, ab); o0[d] = qr0[d] + (aa + ab) * it0;
            upk(acc1[d], aa, ab); o1[d] = qr1[d] + (aa + ab) * it1;
        }
    }
}

// ---------------------------------------------------------------------------
// Pooled tokens: 8-way row split per (b, tok) + smem reduce.
// ---------------------------------------------------------------------------
__global__ void __launch_bounds__(640) mean_kernel(const float* __restrict__ x,
                                                   const float* __restrict__ out) {
    __shared__ float red[8][78];
    int b = blockIdx.x, tok = blockIdx.y, t = threadIdx.x;
    if (t < 624) {
        int g = t / 78, c = t % 78;
        float s = 0.f;
        if (tok == 0) {
            const float* p = x + (size_t)b * 1024 * 78 + c;
            for (int i = g; i < 1024; i += 8) s += p[(size_t)i * 78];
        } else {
            int r0 = (tok == 1) ? 0 : 2048;
            const float* p = out + ((size_t)b * OUT_ROWS + r0) * 78 + c;
            for (int i = g; i < 2048; i += 8) s += p[(size_t)i * 78];
        }
        red[g][c] = s;
    }
    __syncthreads();
    if (t < 78) {
        float tot = 0.f;
        #pragma unroll
        for (int g = 0; g < 8; ++g) tot += red[g][t];
        g_tok[(b * 3 + tok) * 78 + t] = tot * (1.f / 1024.f);
    }
}

// ---------------------------------------------------------------------------
// Tiny 3-token MHSA on pooled tokens -> output rows 4096..4098.
// ---------------------------------------------------------------------------
__global__ void __launch_bounds__(704) fused_kernel(const float* __restrict__ Wq,
                                                    const float* __restrict__ Wk,
                                                    const float* __restrict__ Wv,
                                                    float* __restrict__ out) {
    __shared__ float tok[3][78];
    __shared__ float qs[3][78], ks[3][78], vs[3][78];
    __shared__ float ps[6][3][3];
    int b = blockIdx.x, t = threadIdx.x;

    for (int idx = t; idx < 234; idx += 704) tok[idx / 78][idx % 78] = g_tok[b * 234 + idx];
    __syncthreads();

    if (t < 702) {
        int comp = t / 234, rem = t % 234, i = rem / 78, c = rem % 78;
        const float* W = (comp == 0) ? Wq : ((comp == 1) ? Wk : Wv);
        float a = 0.f;
        #pragma unroll 13
        for (int k = 0; k < 78; ++k) a = fmaf(tok[i][k], __ldg(&W[k * 78 + c]), a);
        float (*dst)[78] = (comp == 0) ? qs : ((comp == 1) ? ks : vs);
        dst[i][c] = a;
    }
    __syncthreads();

    if (t < 54) {
        int h = t / 9, rem = t % 9, i = rem / 3, j = rem % 3;
        float s = 0.f;
        #pragma unroll
        for (int d = 0; d < 13; ++d) s = fmaf(qs[i][h * 13 + d], ks[j][h * 13 + d], s);
        ps[h][i][j] = s * SCALE;
    }
    __syncthreads();

    if (t < 18) {
        int h = t / 3, i = t % 3;
        float a = ps[h][i][0], bb = ps[h][i][1], c = ps[h][i][2];
        float mx = fmaxf(a, fmaxf(bb, c));
        float ea = ex2((a - mx) * L2E), eb = ex2((bb - mx) * L2E), ec = ex2((c - mx) * L2E);
        float inv = 1.f / (ea + eb + ec);
        ps[h][i][0] = ea * inv; ps[h][i][1] = eb * inv; ps[h][i][2] = ec * inv;
    }
    __syncthreads();

    if (t < 78) {
        int h = t / 13;
        #pragma unroll
        for (int i = 0; i < 3; ++i) {
            float o = ps[h][i][0] * vs[0][t] + ps[h][i][1] * vs[1][t] + ps[h][i][2] * vs[2][t];
            out[((size_t)b * OUT_ROWS + 4096 + i) * 78 + t] = o;
        }
    }
}

// ---------------------------------------------------------------------------
extern "C" void kernel_launch(void* const* d_in, const int* in_sizes, int n_in,
                              void* d_out, int out_size) {
    PtrPack p;
    p.x = (const float*)d_in[0];
    p.y = (const float*)d_in[1];
    p.z = (const float*)d_in[2];
    const int widx[12] = {5, 8, 11, 14,   // Q: tv, ta, ctv, cta
                          6, 9, 12, 15,   // K
                          7, 10, 13, 16}; // V
    for (int i = 0; i < 12; ++i) p.W[i] = (const float*)d_in[widx[i]];
    float* out = (float*)d_out;

    proj_kernel<<<dim3(128, 12), 320>>>(p);
    attn_kernel<<<dim3(2, 6, 32), 256>>>(out);
    mean_kernel<<<dim3(8, 3), 640>>>((const float*)d_in[0], out);
    fused_kernel<<<8, 704>>>((const float*)d_in[17], (const float*)d_in[18],
                             (const float*)d_in[19], out);
}